// round 8
// baseline (speedup 1.0000x reference)
#include <cuda_runtime.h>
#include <cstdint>

#define B_    2
#define S_    1024
#define HQ_   32
#define HKV_  8
#define D_    128
#define BQ    64
#define BK    64
#define NT    256

// smem word offsets (fragment-major layouts)
#define W_QF   0          // [4 wq][16 kk][32 slot][4]          = 8192
#define W_KF   8192       // [2 wk][4 n][16 kk][32 slot][2]     = 8192
#define W_VF   16384      // [2 wk][4 kk][16 n][32 slot][2]     = 8192
#define W_PF   24576      // [8 warp][4 kk][32 slot][4]         = 4096
#define W_MLX  28672      // [64][2]
#define W_TOT  28800      // 115,200 B -> 2 CTAs/SM

static __device__ __forceinline__ uint32_t f2tf(float x) {
    uint32_t u; asm("cvt.rna.tf32.f32 %0, %1;" : "=r"(u) : "f"(x)); return u;
}
static __device__ __forceinline__ void mma8(float* d, const uint32_t* a,
                                            uint32_t b0, uint32_t b1) {
    asm volatile(
        "mma.sync.aligned.m16n8k8.row.col.f32.tf32.tf32.f32 "
        "{%0,%1,%2,%3}, {%4,%5,%6,%7}, {%8,%9}, {%0,%1,%2,%3};"
        : "+f"(d[0]), "+f"(d[1]), "+f"(d[2]), "+f"(d[3])
        : "r"(a[0]), "r"(a[1]), "r"(a[2]), "r"(a[3]), "r"(b0), "r"(b1));
}

// -------------------------------------------------------------------------
// KV-cache scatter (unchanged — negligible)
// -------------------------------------------------------------------------
__global__ void kv_scatter_kernel(const float* __restrict__ xk,
                                  const float* __restrict__ xv,
                                  const int* __restrict__ idx,
                                  float* __restrict__ kvout) {
    int t = blockIdx.x * blockDim.x + threadIdx.x;
    const int total = B_ * S_ * 2 * HKV_ * (D_ / 4);
    if (t >= total) return;
    int d4 = t & 31;
    int hh = (t >> 5) & 15;
    int i  = t >> 9;
    float4 v;
    if (hh < HKV_)
        v = reinterpret_cast<const float4*>(xk)[(i * HKV_ + hh) * 32 + d4];
    else
        v = reinterpret_cast<const float4*>(xv)[(i * HKV_ + (hh - HKV_)) * 32 + d4];
    int row = idx[i];
    reinterpret_cast<float4*>(kvout)[((size_t)row * 16 + hh) * 32 + d4] = v;
}

// -------------------------------------------------------------------------
// Split-K tf32 flash attention, fragment-major smem, 2 CTAs/SM.
// 8 warps: wq=w>>1 owns q rows 16*wq..+15; wk=w&1 owns keys wk*32..+31.
// All smem tiles are stored pre-permuted into mma fragment order:
//   Qf: per (wq,kk) an LDS.128 yields the A fragment.
//   Kf: per (wk,n,kk) an LDS.64 yields the B pair (b0,b1).
//   Vf: per (wk,kk,n) an LDS.64 yields the PV B pair.
//   Pf: warp-private; per kk an LDS.128 yields the PV A fragment.
// XOR swizzles keep the scatter-stores conflict-free. 2 barriers/tile.
// -------------------------------------------------------------------------
__global__ __launch_bounds__(NT, 2)
void attn_mma(const float* __restrict__ xq, const float* __restrict__ xk,
              const float* __restrict__ xv, float* __restrict__ out) {
    extern __shared__ uint32_t sm[];
    float* mlx  = (float*)(sm + W_MLX);
    float* Ored = (float*)(sm + W_KF);    // epilogue alias over Kf/Vf

    const int tid = threadIdx.x, w = tid >> 5, lane = tid & 31;
    const int wq = w >> 1, wk = w & 1;
    const int g = lane >> 2, t = lane & 3;
    const int qt = (S_ / BQ - 1) - blockIdx.x;   // big tiles first
    const int h = blockIdx.y, b = blockIdx.z, hk = h >> 2;
    const int m0 = wq * 16, ko = wk * 32;
    const int r0loc = m0 + g, r1loc = m0 + g + 8;
    const float scale = 0.08838834764831845f;    // 1/sqrt(128)

    const uint32_t qf_rd = W_QF + wq * 2048;
    const uint32_t kf_rd = W_KF + wk * 4096;
    const uint32_t vf_rd = W_VF + wk * 4096;
    const uint32_t pf_b  = W_PF + w * 512;

    // ---- Q tile: global -> scaled tf32 -> fragment-major scatter ----
#pragma unroll
    for (int i = 0; i < 8; ++i) {
        int it = tid + i * NT;
        int r = it >> 5, cq = it & 31;
        float4 v = *reinterpret_cast<const float4*>(
            xq + ((((size_t)b * S_ + (size_t)qt * BQ + r) * HQ_ + h) * D_ + cq * 4));
        uint32_t val[4];
        val[0] = f2tf(v.x * scale); val[1] = f2tf(v.y * scale);
        val[2] = f2tf(v.z * scale); val[3] = f2tf(v.w * scale);
        uint32_t base = W_QF + (r >> 4) * 2048 + (cq >> 1) * 128;
        uint32_t j    = (cq & 1) * 2 + ((r >> 3) & 1);
        uint32_t gx   = (r & 7) * 4;
        uint32_t kx   = ((cq >> 1) & 7) << 2;
#pragma unroll
        for (int jj = 0; jj < 4; ++jj)
            sm[base + (((gx + jj) * 4 + j) ^ kx)] = val[jj];
    }

    float Oa[16][4];
#pragma unroll
    for (int n = 0; n < 16; ++n)
#pragma unroll
        for (int c = 0; c < 4; ++c) Oa[n][c] = 0.0f;
    float mr0 = -1e30f, mr1 = -1e30f, lr0 = 0.0f, lr1 = 0.0f;

    for (int kt = 0; kt <= qt; ++kt) {
        __syncthreads();   // B1: prior tile's K/V readers done (kt=0: Q stores)

        // ---- K,V tile: global -> tf32 -> fragment-major scatter ----
#pragma unroll
        for (int i = 0; i < 8; ++i) {
            int it = tid + i * NT;
            int r = it >> 5, cq = it & 31;
            size_t ga = (((size_t)b * S_ + (size_t)kt * BK + r) * HKV_ + hk) * D_
                        + cq * 4;
            float4 kv = *reinterpret_cast<const float4*>(xk + ga);
            float4 vv = *reinterpret_cast<const float4*>(xv + ga);
            uint32_t ku[4], vu[4];
            ku[0] = f2tf(kv.x); ku[1] = f2tf(kv.y); ku[2] = f2tf(kv.z); ku[3] = f2tf(kv.w);
            vu[0] = f2tf(vv.x); vu[1] = f2tf(vv.y); vu[2] = f2tf(vv.z); vu[3] = f2tf(vv.w);
            // K scatter: row fields
            uint32_t kb = W_KF + (r >> 5) * 4096 + ((r >> 3) & 3) * 1024
                        + (cq >> 1) * 64;
            uint32_t kch = cq & 1;
            uint32_t kx = ((cq >> 1) & 15) << 1;
            uint32_t kg = (r & 7) * 4;
#pragma unroll
            for (int jj = 0; jj < 4; ++jj)
                sm[kb + (((kg + jj) * 2 + kch) ^ kx)] = ku[jj];
            // V scatter
            uint32_t vb = W_VF + (r >> 5) * 4096 + ((r >> 3) & 3) * 1024
                        + (cq >> 1) * 64;
            uint32_t vrh = (r >> 2) & 1, vt = r & 3;
            uint32_t vx = ((cq >> 1) & 15) << 1;
            uint32_t gg0 = 4 * (cq & 1);
#pragma unroll
            for (int jj = 0; jj < 4; ++jj)
                sm[vb + (((((gg0 + jj) * 4 + vt) * 2) + vrh) ^ vx)] = vu[jj];
        }
        __syncthreads();   // B2: K/V visible

        // ---- QK^T on own 32-key slice: S(16x32) ----
        float Sa[4][4];
#pragma unroll
        for (int n = 0; n < 4; ++n)
#pragma unroll
            for (int c = 0; c < 4; ++c) Sa[n][c] = 0.0f;
#pragma unroll
        for (int kk = 0; kk < 16; ++kk) {
            uint4 qa = *reinterpret_cast<const uint4*>(
                sm + qf_rd + kk * 128 + ((lane ^ (kk & 7)) << 2));
            uint32_t a[4] = {qa.x, qa.y, qa.z, qa.w};
            const uint32_t koffs = kf_rd + kk * 64 + ((lane ^ (kk & 15)) << 1);
#pragma unroll
            for (int n = 0; n < 4; ++n) {
                uint2 kb2 = *reinterpret_cast<const uint2*>(sm + koffs + n * 1024);
                mma8(Sa[n], a, kb2.x, kb2.y);
            }
        }

        // ---- causal mask (diag tile only) ----
        if (kt == qt) {
#pragma unroll
            for (int n = 0; n < 4; ++n) {
                int c = ko + n * 8 + 2 * t;
                if (c     > r0loc) Sa[n][0] = -1e30f;
                if (c + 1 > r0loc) Sa[n][1] = -1e30f;
                if (c     > r1loc) Sa[n][2] = -1e30f;
                if (c + 1 > r1loc) Sa[n][3] = -1e30f;
            }
        }

        // ---- private online softmax ----
        float t0 = -1e30f, t1 = -1e30f;
#pragma unroll
        for (int n = 0; n < 4; ++n) {
            t0 = fmaxf(t0, fmaxf(Sa[n][0], Sa[n][1]));
            t1 = fmaxf(t1, fmaxf(Sa[n][2], Sa[n][3]));
        }
        t0 = fmaxf(t0, __shfl_xor_sync(0xffffffffu, t0, 1));
        t0 = fmaxf(t0, __shfl_xor_sync(0xffffffffu, t0, 2));
        t1 = fmaxf(t1, __shfl_xor_sync(0xffffffffu, t1, 1));
        t1 = fmaxf(t1, __shfl_xor_sync(0xffffffffu, t1, 2));
        const float M0 = fmaxf(mr0, t0), M1 = fmaxf(mr1, t1);
        const float f0 = __expf(mr0 - M0), f1 = __expf(mr1 - M1);
        mr0 = M0; mr1 = M1;

        // ---- exp + P scatter into warp-private Pf (A-fragment order) ----
        const int ch = t >> 1;                    // (2t)>>2
        const int tl0 = (2 * t) & 3, tl1 = (2 * t + 1) & 3;
        float s0 = 0.0f, s1 = 0.0f;
#pragma unroll
        for (int n = 0; n < 4; ++n) {
            float p00 = __expf(Sa[n][0] - M0), p01 = __expf(Sa[n][1] - M0);
            float p10 = __expf(Sa[n][2] - M1), p11 = __expf(Sa[n][3] - M1);
            s0 += p00 + p01; s1 += p10 + p11;
            uint32_t pb = pf_b + n * 128 + ch * 2;
            sm[pb + ((tl0 * 8 + g) << 2) + 0] = f2tf(p00);
            sm[pb + ((tl1 * 8 + g) << 2) + 0] = f2tf(p01);
            sm[pb + ((tl0 * 8 + g) << 2) + 1] = f2tf(p10);
            sm[pb + ((tl1 * 8 + g) << 2) + 1] = f2tf(p11);
        }
        s0 += __shfl_xor_sync(0xffffffffu, s0, 1);
        s0 += __shfl_xor_sync(0xffffffffu, s0, 2);
        s1 += __shfl_xor_sync(0xffffffffu, s1, 1);
        s1 += __shfl_xor_sync(0xffffffffu, s1, 2);
        lr0 = lr0 * f0 + s0;
        lr1 = lr1 * f1 + s1;
        __syncwarp();      // Pf is warp-private: intra-warp visibility

        // ---- rescale O, PV on own key slice ----
#pragma unroll
        for (int n = 0; n < 16; ++n) {
            Oa[n][0] *= f0; Oa[n][1] *= f0; Oa[n][2] *= f1; Oa[n][3] *= f1;
        }
#pragma unroll
        for (int kk = 0; kk < 4; ++kk) {
            uint4 pa = *reinterpret_cast<const uint4*>(
                sm + pf_b + kk * 128 + ((t * 8 + g) << 2));
            uint32_t a[4] = {pa.x, pa.y, pa.z, pa.w};
            const uint32_t vbase = vf_rd + kk * 1024;
#pragma unroll
            for (int n = 0; n < 16; ++n) {
                uint2 vv2 = *reinterpret_cast<const uint2*>(
                    sm + vbase + n * 64 + ((lane ^ (n & 15)) << 1));
                mma8(Oa[n], a, vv2.x, vv2.y);
            }
        }
    }

    // ---- epilogue: two-way flash merge of the private halves ----
    __syncthreads();       // main loop done; Kf/Vf dead -> reuse as Ored
    if (wk == 1) {
#pragma unroll
        for (int n = 0; n < 16; ++n) {
            float* o0 = Ored + r0loc * 132 + n * 8 + 2 * t;
            o0[0] = Oa[n][0]; o0[1] = Oa[n][1];
            float* o1 = Ored + r1loc * 132 + n * 8 + 2 * t;
            o1[0] = Oa[n][2]; o1[1] = Oa[n][3];
        }
        if (t == 0) {
            mlx[2 * r0loc] = mr0; mlx[2 * r0loc + 1] = lr0;
            mlx[2 * r1loc] = mr1; mlx[2 * r1loc + 1] = lr1;
        }
    }
    __syncthreads();
    if (wk == 0) {
        const float m1a = mlx[2 * r0loc], l1a = mlx[2 * r0loc + 1];
        const float m1b = mlx[2 * r1loc], l1b = mlx[2 * r1loc + 1];
        const float Ma = fmaxf(mr0, m1a), Mb = fmaxf(mr1, m1b);
        const float c0a = __expf(mr0 - Ma), c1a = __expf(m1a - Ma);
        const float c0b = __expf(mr1 - Mb), c1b = __expf(m1b - Mb);
        const float inva = 1.0f / (lr0 * c0a + l1a * c1a);
        const float invb = 1.0f / (lr1 * c0b + l1b * c1b);
        const int q0g = qt * BQ + r0loc, q1g = qt * BQ + r1loc;
        float* ob0 = out + (((size_t)b * S_ + q0g) * HQ_ + h) * D_;
        float* ob1 = out + (((size_t)b * S_ + q1g) * HQ_ + h) * D_;
#pragma unroll
        for (int n = 0; n < 16; ++n) {
            int col = n * 8 + 2 * t;
            float2 o0, o1;
            o0.x = (Oa[n][0] * c0a + Ored[r0loc * 132 + col]     * c1a) * inva;
            o0.y = (Oa[n][1] * c0a + Ored[r0loc * 132 + col + 1] * c1a) * inva;
            o1.x = (Oa[n][2] * c0b + Ored[r1loc * 132 + col]     * c1b) * invb;
            o1.y = (Oa[n][3] * c0b + Ored[r1loc * 132 + col + 1] * c1b) * invb;
            *reinterpret_cast<float2*>(ob0 + col) = o0;
            *reinterpret_cast<float2*>(ob1 + col) = o1;
        }
    }
}

// -------------------------------------------------------------------------
extern "C" void kernel_launch(void* const* d_in, const int* in_sizes, int n_in,
                              void* d_out, int out_size) {
    const float* xq    = (const float*)d_in[0];
    const float* xk    = (const float*)d_in[1];
    const float* xv    = (const float*)d_in[2];
    const float* kvbuf = (const float*)d_in[3];
    const int*   idx   = (const int*)d_in[4];

    float* out   = (float*)d_out;
    float* kvout = out + (size_t)B_ * S_ * HQ_ * D_;

    cudaMemcpyAsync(kvout, kvbuf, (size_t)B_ * S_ * 2 * HKV_ * D_ * sizeof(float),
                    cudaMemcpyDeviceToDevice, 0);
    const int nvec = B_ * S_ * 2 * HKV_ * (D_ / 4);
    kv_scatter_kernel<<<(nvec + 255) / 256, 256>>>(xk, xv, idx, kvout);

    const int smem_bytes = W_TOT * (int)sizeof(uint32_t);   // 115,200
    cudaFuncSetAttribute(attn_mma,
                         cudaFuncAttributeMaxDynamicSharedMemorySize, smem_bytes);
    attn_mma<<<dim3(S_ / BQ, HQ_, B_), NT, smem_bytes>>>(xq, xk, xv, out);
}